// round 16
// baseline (speedup 1.0000x reference)
#include <cuda_runtime.h>
#include <cuda_fp16.h>
#include <math.h>
#include <stdint.h>

#define HDIM 1024
#define IC   4096
#define PH   4096
#define TH   2048
#define NTILES 30
#define MAXM 14592

#if defined(__CUDA_ARCH__)
#  if defined(__CUDA_ARCH_FEAT_SM103_ALL) || defined(__CUDA_ARCH_FEAT_SM100_ALL) || \
      defined(__CUDA_ARCH_FEAT_SM101_ALL) || \
      (defined(__CUDA_ARCH_SPECIFIC__) && (__CUDA_ARCH_SPECIFIC__ >= 1000))
#    define HAS_TCGEN05 1
#  else
#    define HAS_TCGEN05 0
#  endif
#else
#  define HAS_TCGEN05 0
#endif

// ------------------------- device scratch (no allocs) -----------------------
__device__ int    g_meta[NTILES * 4];
__device__ __half g_X [(size_t)MAXM * IC];     // post-LN fp16
__device__ __half g_H [(size_t)MAXM * PH];     // post-GELU fp16
__device__ __half g_W1[(size_t)PH * IC];       // W1^T fp16 [N,K]
__device__ __half g_W2[(size_t)TH * PH];       // W2^T fp16 [N,K]

// ------------------------------ helpers ------------------------------------
__device__ __forceinline__ float gelu_exact(float x) {
    return 0.5f * x * (1.0f + erff(x * 0.70710678118654752440f));
}

#if HAS_TCGEN05
__device__ __forceinline__ uint32_t smem_u32(const void* p) {
    uint32_t a;
    asm("{ .reg .u64 t; cvta.to.shared.u64 t, %1; cvt.u32.u64 %0, t; }" : "=r"(a) : "l"(p));
    return a;
}

__device__ __forceinline__ uint32_t elect_one_pred() {
    uint32_t pred;
    asm volatile(
        "{\n\t.reg .pred p;\n\t"
        "elect.sync _|p, 0xFFFFFFFF;\n\t"
        "selp.b32 %0, 1, 0, p;\n\t}"
        : "=r"(pred));
    return pred;
}

__device__ __forceinline__ void mbar_init(uint32_t m, uint32_t cnt) {
    asm volatile("mbarrier.init.shared.b64 [%0], %1;" :: "r"(m), "r"(cnt) : "memory");
}
__device__ __forceinline__ void mbar_inval(uint32_t m) {
    asm volatile("mbarrier.inval.shared.b64 [%0];" :: "r"(m) : "memory");
}
__device__ __forceinline__ void mbar_wait(uint32_t m, uint32_t phase) {
    asm volatile(
        "{\n\t.reg .pred P;\n\t"
        "LAB_WAIT_%=:\n\t"
        "mbarrier.try_wait.parity.acquire.cta.shared::cta.b64 P, [%0], %1, 0x989680;\n\t"
        "@P bra LAB_DONE_%=;\n\t"
        "bra LAB_WAIT_%=;\n\t"
        "LAB_DONE_%=:\n\t}"
        :: "r"(m), "r"(phase) : "memory");
}

__device__ __forceinline__ void cp_async16(uint32_t dst, const void* src) {
    asm volatile("cp.async.cg.shared.global [%0], [%1], 16;" :: "r"(dst), "l"(src) : "memory");
}
__device__ __forceinline__ void cp_commit() {
    asm volatile("cp.async.commit_group;" ::: "memory");
}
__device__ __forceinline__ void cp_wait0() {
    asm volatile("cp.async.wait_group 0;" ::: "memory");
}
__device__ __forceinline__ void cp_wait1() {
    asm volatile("cp.async.wait_group 1;" ::: "memory");
}
__device__ __forceinline__ void fence_proxy_async_cta() {
    asm volatile("fence.proxy.async.shared::cta;" ::: "memory");
}

__device__ __forceinline__ void tmem_alloc(uint32_t smem_dst, uint32_t ncols) {
    asm volatile("tcgen05.alloc.cta_group::1.sync.aligned.shared::cta.b32 [%0], %1;"
                 :: "r"(smem_dst), "r"(ncols) : "memory");
}
__device__ __forceinline__ void tmem_dealloc(uint32_t tmem, uint32_t ncols) {
    asm volatile("tcgen05.dealloc.cta_group::1.sync.aligned.b32 %0, %1;" :: "r"(tmem), "r"(ncols));
}

// SS f16 MMA, cg1, 4-reg disable-lane vector
__device__ __forceinline__ void mma_f16_ss(uint32_t d, uint64_t ad, uint64_t bd,
                                           uint32_t idesc, uint32_t en) {
    asm volatile(
        "{\n\t.reg .pred p;\n\t"
        "setp.ne.u32 p, %4, 0;\n\t"
        "tcgen05.mma.cta_group::1.kind::f16 [%0], %1, %2, %3, {%5, %5, %5, %5}, p;\n\t}"
        :: "r"(d), "l"(ad), "l"(bd), "r"(idesc), "r"(en), "r"(0u) : "memory");
}

__device__ __forceinline__ void mma_commit(uint32_t mbar) {
    asm volatile(
        "tcgen05.commit.cta_group::1.mbarrier::arrive::one.shared::cluster.b64 [%0];"
        :: "r"(mbar) : "memory");
}

#define TCGEN05_LD_X32(r, addr) \
    asm volatile( \
        "tcgen05.ld.sync.aligned.32x32b.x32.b32 " \
        "{%0, %1, %2, %3, %4, %5, %6, %7, " \
        " %8, %9, %10, %11, %12, %13, %14, %15, " \
        " %16, %17, %18, %19, %20, %21, %22, %23, " \
        " %24, %25, %26, %27, %28, %29, %30, %31}, [%32];" \
        : "=r"((r)[0]),  "=r"((r)[1]),  "=r"((r)[2]),  "=r"((r)[3]), \
          "=r"((r)[4]),  "=r"((r)[5]),  "=r"((r)[6]),  "=r"((r)[7]), \
          "=r"((r)[8]),  "=r"((r)[9]),  "=r"((r)[10]), "=r"((r)[11]), \
          "=r"((r)[12]), "=r"((r)[13]), "=r"((r)[14]), "=r"((r)[15]), \
          "=r"((r)[16]), "=r"((r)[17]), "=r"((r)[18]), "=r"((r)[19]), \
          "=r"((r)[20]), "=r"((r)[21]), "=r"((r)[22]), "=r"((r)[23]), \
          "=r"((r)[24]), "=r"((r)[25]), "=r"((r)[26]), "=r"((r)[27]), \
          "=r"((r)[28]), "=r"((r)[29]), "=r"((r)[30]), "=r"((r)[31]) \
        : "r"(addr))

__device__ __forceinline__ void tmem_wait_ld() {
    asm volatile("tcgen05.wait::ld.sync.aligned;" ::: "memory");
}
__device__ __forceinline__ void tc_fence_after() {
    asm volatile("tcgen05.fence::after_thread_sync;" ::: "memory");
}
__device__ __forceinline__ void tc_fence_before() {
    asm volatile("tcgen05.fence::before_thread_sync;" ::: "memory");
}

// SW128 K-major descriptor (verified): layout=2, version=1, SBO=64, LBO=1
static __device__ __forceinline__ uint64_t make_desc(uint32_t addr) {
    const uint64_t base = (2ull << 61) | (1ull << 46) | (64ull << 32) | (1ull << 16);
    return base | ((uint64_t)(addr >> 4) & 0x3FFF);
}
#endif  // HAS_TCGEN05

#define SWZ(x) ((x) ^ (((x) >> 3) & 0x70))

// ----------------------------------------------------------------------------
__global__ void meta_kernel(const int* __restrict__ ss) {
    if (threadIdx.x == 0 && blockIdx.x == 0) {
        int is64 = (ss[1] == 0) ? 1 : 0;
        int in_off = 0, out_off = 0;
        for (int t = 0; t < NTILES; t++) {
            int h, w;
            if (is64) { h = ss[4 * t]; w = ss[4 * t + 2]; }
            else      { h = ss[2 * t]; w = ss[2 * t + 1]; }
            g_meta[4 * t + 0] = h;
            g_meta[4 * t + 1] = w;
            g_meta[4 * t + 2] = in_off;
            g_meta[4 * t + 3] = out_off;
            in_off  += h * w;
            out_off += (h >> 1) * (w >> 1);
        }
    }
}

// ----------------------------------------------------------------------------
// gather + LayerNorm -> fp16
// ----------------------------------------------------------------------------
__global__ void __launch_bounds__(256) gather_ln_kernel(
    const float* __restrict__ vf,
    const float* __restrict__ gamma,
    const float* __restrict__ beta)
{
    const int r   = blockIdx.x;
    const int tid = threadIdx.x;

    __shared__ int   srows[4];
    __shared__ float sred[2][8];
    __shared__ float sstat[2];

    if (tid == 0) {
        int t = 0;
        #pragma unroll 1
        for (int i = 0; i < NTILES; i++) {
            int h  = g_meta[4 * i + 0];
            int w  = g_meta[4 * i + 1];
            int oo = g_meta[4 * i + 3];
            int cnt = (h >> 1) * (w >> 1);
            if (r >= oo && r < oo + cnt) { t = i; break; }
        }
        int w  = g_meta[4 * t + 1];
        int io = g_meta[4 * t + 2];
        int oo = g_meta[4 * t + 3];
        int local = r - oo;
        int wb = w >> 1;
        int bh = local / wb;
        int bw = local - bh * wb;
        srows[0] = io + (2 * bh)     * w + 2 * bw;
        srows[1] = io + (2 * bh)     * w + 2 * bw + 1;
        srows[2] = io + (2 * bh + 1) * w + 2 * bw;
        srows[3] = io + (2 * bh + 1) * w + 2 * bw + 1;
    }
    __syncthreads();

    float vals[16];
    float s = 0.f, s2 = 0.f;
    #pragma unroll
    for (int i = 0; i < 16; i++) {
        int f      = tid + i * 256;
        int c      = f >> 10;
        int within = f & 1023;
        float v = vf[(size_t)srows[c] * HDIM + within];
        vals[i] = v;
        s  += v;
        s2 += v * v;
    }

    #pragma unroll
    for (int o = 16; o > 0; o >>= 1) {
        s  += __shfl_down_sync(0xFFFFFFFFu, s, o);
        s2 += __shfl_down_sync(0xFFFFFFFFu, s2, o);
    }
    if ((tid & 31) == 0) { sred[0][tid >> 5] = s; sred[1][tid >> 5] = s2; }
    __syncthreads();
    if (tid < 32) {
        float a = (tid < 8) ? sred[0][tid] : 0.f;
        float b = (tid < 8) ? sred[1][tid] : 0.f;
        #pragma unroll
        for (int o = 4; o > 0; o >>= 1) {
            a += __shfl_down_sync(0xFFFFFFFFu, a, o);
            b += __shfl_down_sync(0xFFFFFFFFu, b, o);
        }
        if (tid == 0) {
            float mu  = a * (1.0f / IC);
            float var = b * (1.0f / IC) - mu * mu;
            sstat[0] = mu;
            sstat[1] = rsqrtf(var + 1e-5f);
        }
    }
    __syncthreads();

    float mu   = sstat[0];
    float rstd = sstat[1];
    size_t rowb = (size_t)r * IC;
    #pragma unroll
    for (int i = 0; i < 16; i++) {
        int f = tid + i * 256;
        float y = (vals[i] - mu) * rstd * gamma[f] + beta[f];
        g_X[rowb + f] = __float2half_rn(y);
    }
}

// ----------------------------------------------------------------------------
// weight transpose + fp16 convert:  W[K,N] fp32 -> T [N,K] fp16
// ----------------------------------------------------------------------------
__global__ void __launch_bounds__(256) wconv_kernel(
    const float* __restrict__ W,
    __half* __restrict__ T,
    int K, int N)
{
    __shared__ float tile[32][33];
    int tx = threadIdx.x, ty = threadIdx.y;         // 32 x 8
    int n0 = blockIdx.x * 32, k0 = blockIdx.y * 32;
    #pragma unroll
    for (int j = 0; j < 4; j++)
        tile[ty + 8 * j][tx] = W[(size_t)(k0 + ty + 8 * j) * N + n0 + tx];
    __syncthreads();
    #pragma unroll
    for (int j = 0; j < 4; j++) {
        float v = tile[tx][ty + 8 * j];
        T[(size_t)(n0 + ty + 8 * j) * K + k0 + tx] = __float2half_rn(v);
    }
}

// ----------------------------------------------------------------------------
// Persistent tcgen05 SS fp16 GEMM, 256x256 tiles, KCHUNK=64, SW128, 3 stages.
//   Each CTA loops over tiles; the cp.async pipeline runs continuously across
//   tile boundaries (global chunk counter gq, stage = gq % 3), so the next
//   tile's loads stream during the current tile's epilogue and the pipeline
//   prologue is paid once per CTA.  Tile order is M-major within a wave so
//   concurrent CTAs share one B (weight) column -> W stays L2-hot.
// ----------------------------------------------------------------------------
#define KCHUNK  64
#define NCHUNK  64            // K = 4096 for both GEMMs
#define STAGEB  65536
#define NSTG    3
#define DSMEMB  (NSTG * STAGEB + 1024)
#define IDESC_V ((1u<<4)|(32u<<17)|(8u<<24))   // fp16 in, f32 acc, N=256, M=128

__global__ void __launch_bounds__(256) __cluster_dims__(1, 1, 1) gemm_kernel(
    const __half* __restrict__ A,
    const __half* __restrict__ B,
    const float* __restrict__ bias,
    float* __restrict__ outF,
    __half* __restrict__ outH,
    int M, int K, int Nfull, int mode)
{
#if HAS_TCGEN05
    extern __shared__ char dsm_raw[];
    __shared__ __align__(8) uint64_t s_bar[1];
    __shared__ __align__(4) uint32_t s_tmem[1];

    const int tid = threadIdx.x;
    const int wid = tid >> 5;
    const int ntm = M >> 8;                      // M tiles (57)
    const int total_tiles = ntm * (Nfull >> 8);
    const int myntiles = (total_tiles - blockIdx.x + gridDim.x - 1) / gridDim.x;
    const int gq_total = myntiles * NCHUNK;

    uint32_t stage = (smem_u32(dsm_raw) + 1023u) & ~1023u;
    uint32_t bMma  = smem_u32(&s_bar[0]);

    if (wid == 0) tmem_alloc(smem_u32(s_tmem), 512);
    if (tid == 0) mbar_init(bMma, 1);
    __syncthreads();
    uint32_t tmem;
    asm volatile("ld.shared.b32 %0, [%1];" : "=r"(tmem) : "r"(smem_u32(s_tmem)));

    const size_t kb = (size_t)K * 2;   // row bytes (fp16)

    // load chunk #gq (global) into stage gq % 3
    auto load_chunk = [&](int gq) {
        int t  = blockIdx.x + (gq >> 6) * gridDim.x;
        int bm = (t % ntm) << 8;
        int bn = (t / ntm) << 8;
        int c  = gq & 63;
        uint32_t sb = stage + (uint32_t)(gq % NSTG) * STAGEB;
        size_t koff = (size_t)c * (KCHUNK * 2);   // 128 bytes per chunk
        #pragma unroll
        for (int i = 0; i < 16; ++i) {
            int q = tid + 256 * i;
            const char* src;
            uint32_t dst;
            if (q < 2048) {                 // A: 2 subtiles x 128 rows x 8 ch
                int plane = q >> 10;
                int idx   = q & 1023;
                int row   = idx >> 3;
                int ch    = idx & 7;
                int grow  = bm + plane * 128 + row;
                src = (const char*)A + (size_t)grow * kb + koff + ch * 16;
                dst = sb + plane * 16384 + SWZ(row * 128 + ch * 16);
            } else {                        // B: 256 rows x 8 ch
                int idx   = q - 2048;
                int row   = idx >> 3;
                int ch    = idx & 7;
                int grow  = bn + row;
                src = (const char*)B + (size_t)grow * kb + koff + ch * 16;
                dst = sb + 32768 + SWZ(row * 128 + ch * 16);
            }
            cp_async16(dst, src);
        }
        cp_commit();
    };

    // prologue: two chunks in flight (once per CTA)
    load_chunk(0);
    if (gq_total > 1) load_chunk(1);

    const int lane = tid & 31;
    const int sub  = wid & 3;
    const int tI   = wid >> 2;
    const uint32_t woff = ((uint32_t)sub) << 21;

    int gq = 0;
    for (int it = 0; it < myntiles; ++it) {
        int t  = blockIdx.x + it * gridDim.x;
        int bm = (t % ntm) << 8;
        int bn = (t / ntm) << 8;

        for (int c = 0; c < NCHUNK; ++c, ++gq) {
            if (gq + 1 < gq_total) cp_wait1();
            else                   cp_wait0();
            fence_proxy_async_cta();
            tc_fence_before();
            __syncthreads();

            if (gq + 2 < gq_total) {
                if (gq >= 1) mbar_wait(bMma, (uint32_t)((gq - 1) & 1));
                load_chunk(gq + 2);
            }

            if (wid == 0) {
                tc_fence_after();
                if (elect_one_pred()) {
                    uint32_t sb = stage + (uint32_t)(gq % NSTG) * STAGEB;
                    uint64_t dA0 = make_desc(sb);
                    uint64_t dA1 = make_desc(sb + 16384);
                    uint64_t dB  = make_desc(sb + 32768);
                    #pragma unroll
                    for (int ks = 0; ks < 4; ++ks) {
                        uint64_t o = (uint64_t)(ks * 2);
                        uint32_t acc = (c > 0 || ks > 0) ? 1u : 0u;
                        mma_f16_ss(tmem,       dA0 + o, dB + o, IDESC_V, acc);
                        mma_f16_ss(tmem + 256, dA1 + o, dB + o, IDESC_V, acc);
                    }
                    mma_commit(bMma);
                }
            }
        }

        // ---------------- epilogue for tile t (loads of next tile stream) ---
        mbar_wait(bMma, (uint32_t)((gq - 1) & 1));
        __syncthreads();
        tc_fence_after();

        const int row = bm + tI * 128 + sub * 32 + lane;
        #pragma unroll 1
        for (int b = 0; b < 8; ++b) {
            uint32_t r[32];
            TCGEN05_LD_X32(r, tmem + tI * 256 + b * 32 + woff);
            tmem_wait_ld();
            int col0 = bn + b * 32;
            if (mode) {
                __align__(16) __half hv[32];
                #pragma unroll
                for (int j = 0; j < 32; ++j) {
                    float v = __uint_as_float(r[j]) + bias[col0 + j];
                    hv[j] = __float2half_rn(gelu_exact(v));
                }
                uint4* dh = (uint4*)(outH + (size_t)row * Nfull + col0);
                #pragma unroll
                for (int u = 0; u < 4; ++u) dh[u] = ((uint4*)hv)[u];
            } else {
                float* dp = outF + (size_t)row * Nfull + col0;
                #pragma unroll
                for (int j = 0; j < 32; j += 4) {
                    float4 v;
                    v.x = __uint_as_float(r[j + 0]) + bias[col0 + j + 0];
                    v.y = __uint_as_float(r[j + 1]) + bias[col0 + j + 1];
                    v.z = __uint_as_float(r[j + 2]) + bias[col0 + j + 2];
                    v.w = __uint_as_float(r[j + 3]) + bias[col0 + j + 3];
                    *(float4*)(dp + j) = v;
                }
            }
        }

        tc_fence_before();
        __syncthreads();   // all warps done reading TMEM before next tile MMA
    }

    if (tid == 0) mbar_inval(bMma);
    __syncthreads();
    if (wid == 0) tmem_dealloc(tmem, 512);

#else  // ------------------- FFMA fallback (plain sm_103 pass) ---------------
    extern __shared__ char dsm_raw[];
    float* As = (float*)dsm_raw;                  // [16][128]
    float* Bs = (float*)(dsm_raw + 16 * 128 * 4); // [16][64]

    const int tid = threadIdx.x & 127;
    const int ty  = tid >> 4;
    const int tx  = tid & 15;
    if (threadIdx.x >= 128) return;

    const int ntm = M >> 8;
    const int total_tiles = ntm * (Nfull >> 8);

    for (int t = blockIdx.x; t < total_tiles; t += gridDim.x) {
        const int bmT = (t % ntm) << 8;
        const int bn0 = (t / ntm) << 8;
        for (int msub = 0; msub < 2; ++msub) {
            const int bm = bmT + msub * 128;
            for (int ns = 0; ns < 4; ++ns) {
                int bn = bn0 + ns * 64;
                float acc[16][4];
                #pragma unroll
                for (int i = 0; i < 16; i++)
                    #pragma unroll
                    for (int j = 0; j < 4; j++) acc[i][j] = 0.f;

                for (int k0 = 0; k0 < K; k0 += 16) {
                    #pragma unroll
                    for (int i = 0; i < 16; i++) {
                        int idx = tid + 128 * i;
                        int row = idx >> 4, kk = idx & 15;
                        As[kk * 128 + row] = __half2float(A[(size_t)(bm + row) * K + k0 + kk]);
                    }
                    #pragma unroll
                    for (int i = 0; i < 8; i++) {
                        int idx = tid + 128 * i;
                        int n = idx >> 4, kk = idx & 15;
                        Bs[kk * 64 + n] = __half2float(B[(size_t)(bn + n) * K + k0 + kk]);
                    }
                    __syncthreads();
                    #pragma unroll
                    for (int kk = 0; kk < 16; kk++) {
                        float bvals[4];
                        #pragma unroll
                        for (int j = 0; j < 4; j++) bvals[j] = Bs[kk * 64 + tx * 4 + j];
                        #pragma unroll
                        for (int i = 0; i < 16; i++) {
                            float av = As[kk * 128 + ty * 16 + i];
                            #pragma unroll
                            for (int j = 0; j < 4; j++) acc[i][j] += av * bvals[j];
                        }
                    }
                    __syncthreads();
                }

                #pragma unroll
                for (int i = 0; i < 16; i++) {
                    int row = bm + ty * 16 + i;
                    #pragma unroll
                    for (int j = 0; j < 4; j++) {
                        int col = bn + tx * 4 + j;
                        float v = acc[i][j] + bias[col];
                        if (mode) outH[(size_t)row * Nfull + col] = __float2half_rn(gelu_exact(v));
                        else      outF[(size_t)row * Nfull + col] = v;
                    }
                }
                __syncthreads();
            }
        }
    }
#endif
}

// ----------------------------------------------------------------------------
extern "C" void kernel_launch(void* const* d_in, const int* in_sizes, int n_in,
                              void* d_out, int out_size)
{
    const float* vf    = (const float*)d_in[0];
    const int*   ss    = (const int*)  d_in[1];
    const float* gamma = (const float*)d_in[2];
    const float* beta  = (const float*)d_in[3];
    const float* w1    = (const float*)d_in[4];
    const float* b1    = (const float*)d_in[5];
    const float* w2    = (const float*)d_in[6];
    const float* b2    = (const float*)d_in[7];
    float* out = (float*)d_out;

    int total_tokens = in_sizes[0] / HDIM;
    int M = total_tokens / 4;
    if (M > MAXM) M = MAXM;

    __half *dX, *dH, *dW1, *dW2;
    cudaGetSymbolAddress((void**)&dX,  g_X);
    cudaGetSymbolAddress((void**)&dH,  g_H);
    cudaGetSymbolAddress((void**)&dW1, g_W1);
    cudaGetSymbolAddress((void**)&dW2, g_W2);

    int sms = 148;
    cudaDeviceGetAttribute(&sms, cudaDevAttrMultiProcessorCount, 0);

    cudaFuncSetAttribute(gemm_kernel, cudaFuncAttributeMaxDynamicSharedMemorySize, DSMEMB);

    meta_kernel<<<1, 32>>>(ss);
    gather_ln_kernel<<<M, 256>>>(vf, gamma, beta);

    dim3 wb(32, 8);
    wconv_kernel<<<dim3(PH / 32, IC / 32), wb>>>(w1, dW1, IC, PH);
    wconv_kernel<<<dim3(TH / 32, PH / 32), wb>>>(w2, dW2, PH, TH);

    int tt1 = (M / 256) * (PH / 256);
    int g1  = tt1 < sms ? tt1 : sms;
    gemm_kernel<<<g1, 256, DSMEMB>>>(dX, dW1, b1, nullptr, dH, M, IC, PH, 1);

    int tt2 = (M / 256) * (TH / 256);
    int g2  = tt2 < sms ? tt2 : sms;
    gemm_kernel<<<g2, 256, DSMEMB>>>(dH, dW2, b2, out, nullptr, M, PH, TH, 0);
}

// round 17
// speedup vs baseline: 1.0541x; 1.0541x over previous
#include <cuda_runtime.h>
#include <cuda_fp16.h>
#include <math.h>
#include <stdint.h>

#define HDIM 1024
#define IC   4096
#define PH   4096
#define TH   2048
#define NTILES 30
#define MAXM 14592

#if defined(__CUDA_ARCH__)
#  if defined(__CUDA_ARCH_FEAT_SM103_ALL) || defined(__CUDA_ARCH_FEAT_SM100_ALL) || \
      defined(__CUDA_ARCH_FEAT_SM101_ALL) || \
      (defined(__CUDA_ARCH_SPECIFIC__) && (__CUDA_ARCH_SPECIFIC__ >= 1000))
#    define HAS_TCGEN05 1
#  else
#    define HAS_TCGEN05 0
#  endif
#else
#  define HAS_TCGEN05 0
#endif

// ------------------------- device scratch (no allocs) -----------------------
__device__ int    g_meta[NTILES * 4];
__device__ __half g_X [(size_t)MAXM * IC];     // post-LN fp16
__device__ __half g_H [(size_t)MAXM * PH];     // post-GELU fp16
__device__ __half g_W1[(size_t)PH * IC];       // W1^T fp16 [N,K]
__device__ __half g_W2[(size_t)TH * PH];       // W2^T fp16 [N,K]

// ------------------------------ helpers ------------------------------------
__device__ __forceinline__ float gelu_exact(float x) {
    return 0.5f * x * (1.0f + erff(x * 0.70710678118654752440f));
}

#if HAS_TCGEN05
__device__ __forceinline__ uint32_t smem_u32(const void* p) {
    uint32_t a;
    asm("{ .reg .u64 t; cvta.to.shared.u64 t, %1; cvt.u32.u64 %0, t; }" : "=r"(a) : "l"(p));
    return a;
}

__device__ __forceinline__ uint32_t elect_one_pred() {
    uint32_t pred;
    asm volatile(
        "{\n\t.reg .pred p;\n\t"
        "elect.sync _|p, 0xFFFFFFFF;\n\t"
        "selp.b32 %0, 1, 0, p;\n\t}"
        : "=r"(pred));
    return pred;
}

__device__ __forceinline__ void mbar_init(uint32_t m, uint32_t cnt) {
    asm volatile("mbarrier.init.shared.b64 [%0], %1;" :: "r"(m), "r"(cnt) : "memory");
}
__device__ __forceinline__ void mbar_inval(uint32_t m) {
    asm volatile("mbarrier.inval.shared.b64 [%0];" :: "r"(m) : "memory");
}
__device__ __forceinline__ void mbar_wait(uint32_t m, uint32_t phase) {
    asm volatile(
        "{\n\t.reg .pred P;\n\t"
        "LAB_WAIT_%=:\n\t"
        "mbarrier.try_wait.parity.acquire.cta.shared::cta.b64 P, [%0], %1, 0x989680;\n\t"
        "@P bra LAB_DONE_%=;\n\t"
        "bra LAB_WAIT_%=;\n\t"
        "LAB_DONE_%=:\n\t}"
        :: "r"(m), "r"(phase) : "memory");
}

__device__ __forceinline__ void cp_async16(uint32_t dst, const void* src) {
    asm volatile("cp.async.cg.shared.global [%0], [%1], 16;" :: "r"(dst), "l"(src) : "memory");
}
__device__ __forceinline__ void cp_commit() {
    asm volatile("cp.async.commit_group;" ::: "memory");
}
__device__ __forceinline__ void cp_wait0() {
    asm volatile("cp.async.wait_group 0;" ::: "memory");
}
__device__ __forceinline__ void cp_wait1() {
    asm volatile("cp.async.wait_group 1;" ::: "memory");
}
__device__ __forceinline__ void fence_proxy_async_cta() {
    asm volatile("fence.proxy.async.shared::cta;" ::: "memory");
}

__device__ __forceinline__ void tmem_alloc(uint32_t smem_dst, uint32_t ncols) {
    asm volatile("tcgen05.alloc.cta_group::1.sync.aligned.shared::cta.b32 [%0], %1;"
                 :: "r"(smem_dst), "r"(ncols) : "memory");
}
__device__ __forceinline__ void tmem_dealloc(uint32_t tmem, uint32_t ncols) {
    asm volatile("tcgen05.dealloc.cta_group::1.sync.aligned.b32 %0, %1;" :: "r"(tmem), "r"(ncols));
}

// SS f16 MMA, cg1, 4-reg disable-lane vector
__device__ __forceinline__ void mma_f16_ss(uint32_t d, uint64_t ad, uint64_t bd,
                                           uint32_t idesc, uint32_t en) {
    asm volatile(
        "{\n\t.reg .pred p;\n\t"
        "setp.ne.u32 p, %4, 0;\n\t"
        "tcgen05.mma.cta_group::1.kind::f16 [%0], %1, %2, %3, {%5, %5, %5, %5}, p;\n\t}"
        :: "r"(d), "l"(ad), "l"(bd), "r"(idesc), "r"(en), "r"(0u) : "memory");
}

__device__ __forceinline__ void mma_commit(uint32_t mbar) {
    asm volatile(
        "tcgen05.commit.cta_group::1.mbarrier::arrive::one.shared::cluster.b64 [%0];"
        :: "r"(mbar) : "memory");
}

#define TCGEN05_LD_X32(r, addr) \
    asm volatile( \
        "tcgen05.ld.sync.aligned.32x32b.x32.b32 " \
        "{%0, %1, %2, %3, %4, %5, %6, %7, " \
        " %8, %9, %10, %11, %12, %13, %14, %15, " \
        " %16, %17, %18, %19, %20, %21, %22, %23, " \
        " %24, %25, %26, %27, %28, %29, %30, %31}, [%32];" \
        : "=r"((r)[0]),  "=r"((r)[1]),  "=r"((r)[2]),  "=r"((r)[3]), \
          "=r"((r)[4]),  "=r"((r)[5]),  "=r"((r)[6]),  "=r"((r)[7]), \
          "=r"((r)[8]),  "=r"((r)[9]),  "=r"((r)[10]), "=r"((r)[11]), \
          "=r"((r)[12]), "=r"((r)[13]), "=r"((r)[14]), "=r"((r)[15]), \
          "=r"((r)[16]), "=r"((r)[17]), "=r"((r)[18]), "=r"((r)[19]), \
          "=r"((r)[20]), "=r"((r)[21]), "=r"((r)[22]), "=r"((r)[23]), \
          "=r"((r)[24]), "=r"((r)[25]), "=r"((r)[26]), "=r"((r)[27]), \
          "=r"((r)[28]), "=r"((r)[29]), "=r"((r)[30]), "=r"((r)[31]) \
        : "r"(addr))

__device__ __forceinline__ void tmem_wait_ld() {
    asm volatile("tcgen05.wait::ld.sync.aligned;" ::: "memory");
}
__device__ __forceinline__ void tc_fence_after() {
    asm volatile("tcgen05.fence::after_thread_sync;" ::: "memory");
}
__device__ __forceinline__ void tc_fence_before() {
    asm volatile("tcgen05.fence::before_thread_sync;" ::: "memory");
}

// SW128 K-major descriptor (verified): layout=2, version=1, SBO=64, LBO=1
static __device__ __forceinline__ uint64_t make_desc(uint32_t addr) {
    const uint64_t base = (2ull << 61) | (1ull << 46) | (64ull << 32) | (1ull << 16);
    return base | ((uint64_t)(addr >> 4) & 0x3FFF);
}
#endif  // HAS_TCGEN05

#define SWZ(x) ((x) ^ (((x) >> 3) & 0x70))

// ----------------------------------------------------------------------------
__global__ void meta_kernel(const int* __restrict__ ss) {
    if (threadIdx.x == 0 && blockIdx.x == 0) {
        int is64 = (ss[1] == 0) ? 1 : 0;
        int in_off = 0, out_off = 0;
        for (int t = 0; t < NTILES; t++) {
            int h, w;
            if (is64) { h = ss[4 * t]; w = ss[4 * t + 2]; }
            else      { h = ss[2 * t]; w = ss[2 * t + 1]; }
            g_meta[4 * t + 0] = h;
            g_meta[4 * t + 1] = w;
            g_meta[4 * t + 2] = in_off;
            g_meta[4 * t + 3] = out_off;
            in_off  += h * w;
            out_off += (h >> 1) * (w >> 1);
        }
    }
}

// ----------------------------------------------------------------------------
// gather + LayerNorm -> fp16
// ----------------------------------------------------------------------------
__global__ void __launch_bounds__(256) gather_ln_kernel(
    const float* __restrict__ vf,
    const float* __restrict__ gamma,
    const float* __restrict__ beta)
{
    const int r   = blockIdx.x;
    const int tid = threadIdx.x;

    __shared__ int   srows[4];
    __shared__ float sred[2][8];
    __shared__ float sstat[2];

    if (tid == 0) {
        int t = 0;
        #pragma unroll 1
        for (int i = 0; i < NTILES; i++) {
            int h  = g_meta[4 * i + 0];
            int w  = g_meta[4 * i + 1];
            int oo = g_meta[4 * i + 3];
            int cnt = (h >> 1) * (w >> 1);
            if (r >= oo && r < oo + cnt) { t = i; break; }
        }
        int w  = g_meta[4 * t + 1];
        int io = g_meta[4 * t + 2];
        int oo = g_meta[4 * t + 3];
        int local = r - oo;
        int wb = w >> 1;
        int bh = local / wb;
        int bw = local - bh * wb;
        srows[0] = io + (2 * bh)     * w + 2 * bw;
        srows[1] = io + (2 * bh)     * w + 2 * bw + 1;
        srows[2] = io + (2 * bh + 1) * w + 2 * bw;
        srows[3] = io + (2 * bh + 1) * w + 2 * bw + 1;
    }
    __syncthreads();

    float vals[16];
    float s = 0.f, s2 = 0.f;
    #pragma unroll
    for (int i = 0; i < 16; i++) {
        int f      = tid + i * 256;
        int c      = f >> 10;
        int within = f & 1023;
        float v = vf[(size_t)srows[c] * HDIM + within];
        vals[i] = v;
        s  += v;
        s2 += v * v;
    }

    #pragma unroll
    for (int o = 16; o > 0; o >>= 1) {
        s  += __shfl_down_sync(0xFFFFFFFFu, s, o);
        s2 += __shfl_down_sync(0xFFFFFFFFu, s2, o);
    }
    if ((tid & 31) == 0) { sred[0][tid >> 5] = s; sred[1][tid >> 5] = s2; }
    __syncthreads();
    if (tid < 32) {
        float a = (tid < 8) ? sred[0][tid] : 0.f;
        float b = (tid < 8) ? sred[1][tid] : 0.f;
        #pragma unroll
        for (int o = 4; o > 0; o >>= 1) {
            a += __shfl_down_sync(0xFFFFFFFFu, a, o);
            b += __shfl_down_sync(0xFFFFFFFFu, b, o);
        }
        if (tid == 0) {
            float mu  = a * (1.0f / IC);
            float var = b * (1.0f / IC) - mu * mu;
            sstat[0] = mu;
            sstat[1] = rsqrtf(var + 1e-5f);
        }
    }
    __syncthreads();

    float mu   = sstat[0];
    float rstd = sstat[1];
    size_t rowb = (size_t)r * IC;
    #pragma unroll
    for (int i = 0; i < 16; i++) {
        int f = tid + i * 256;
        float y = (vals[i] - mu) * rstd * gamma[f] + beta[f];
        g_X[rowb + f] = __float2half_rn(y);
    }
}

// ----------------------------------------------------------------------------
// weight transpose + fp16 convert:  W[K,N] fp32 -> T [N,K] fp16
// ----------------------------------------------------------------------------
__global__ void __launch_bounds__(256) wconv_kernel(
    const float* __restrict__ W,
    __half* __restrict__ T,
    int K, int N)
{
    __shared__ float tile[32][33];
    int tx = threadIdx.x, ty = threadIdx.y;         // 32 x 8
    int n0 = blockIdx.x * 32, k0 = blockIdx.y * 32;
    #pragma unroll
    for (int j = 0; j < 4; j++)
        tile[ty + 8 * j][tx] = W[(size_t)(k0 + ty + 8 * j) * N + n0 + tx];
    __syncthreads();
    #pragma unroll
    for (int j = 0; j < 4; j++) {
        float v = tile[tx][ty + 8 * j];
        T[(size_t)(n0 + ty + 8 * j) * K + k0 + tx] = __float2half_rn(v);
    }
}

// ----------------------------------------------------------------------------
// Persistent tcgen05 SS fp16 GEMM, 256x256 tiles, KCHUNK=64, SW128, 3 stages.
//   Cross-tile continuous cp.async pipeline (global chunk counter gq).
//   Tile order is N-major (bn = t % nN, bm = t / nN): concurrent CTAs share
//   one bm band, so the L2 working set stays ~52MB (A band + full B) instead
//   of thrashing the whole A matrix (the R16 regression root cause).
// ----------------------------------------------------------------------------
#define KCHUNK  64
#define NCHUNK  64            // K = 4096 for both GEMMs
#define STAGEB  65536
#define NSTG    3
#define DSMEMB  (NSTG * STAGEB + 1024)
#define IDESC_V ((1u<<4)|(32u<<17)|(8u<<24))   // fp16 in, f32 acc, N=256, M=128

__global__ void __launch_bounds__(256) __cluster_dims__(1, 1, 1) gemm_kernel(
    const __half* __restrict__ A,
    const __half* __restrict__ B,
    const float* __restrict__ bias,
    float* __restrict__ outF,
    __half* __restrict__ outH,
    int M, int K, int Nfull, int mode)
{
#if HAS_TCGEN05
    extern __shared__ char dsm_raw[];
    __shared__ __align__(8) uint64_t s_bar[1];
    __shared__ __align__(4) uint32_t s_tmem[1];

    const int tid = threadIdx.x;
    const int wid = tid >> 5;
    const int nN  = Nfull >> 8;                  // N tiles
    const int total_tiles = (M >> 8) * nN;
    const int myntiles = (total_tiles - blockIdx.x + gridDim.x - 1) / gridDim.x;
    const int gq_total = myntiles * NCHUNK;

    uint32_t stage = (smem_u32(dsm_raw) + 1023u) & ~1023u;
    uint32_t bMma  = smem_u32(&s_bar[0]);

    if (wid == 0) tmem_alloc(smem_u32(s_tmem), 512);
    if (tid == 0) mbar_init(bMma, 1);
    __syncthreads();
    uint32_t tmem;
    asm volatile("ld.shared.b32 %0, [%1];" : "=r"(tmem) : "r"(smem_u32(s_tmem)));

    const size_t kb = (size_t)K * 2;   // row bytes (fp16)

    // load chunk #gq (global) into stage gq % 3;  tile map is N-major
    auto load_chunk = [&](int gq) {
        int t  = blockIdx.x + (gq >> 6) * gridDim.x;
        int bn = (t % nN) << 8;
        int bm = (t / nN) << 8;
        int c  = gq & 63;
        uint32_t sb = stage + (uint32_t)(gq % NSTG) * STAGEB;
        size_t koff = (size_t)c * (KCHUNK * 2);   // 128 bytes per chunk
        #pragma unroll
        for (int i = 0; i < 16; ++i) {
            int q = tid + 256 * i;
            const char* src;
            uint32_t dst;
            if (q < 2048) {                 // A: 2 subtiles x 128 rows x 8 ch
                int plane = q >> 10;
                int idx   = q & 1023;
                int row   = idx >> 3;
                int ch    = idx & 7;
                int grow  = bm + plane * 128 + row;
                src = (const char*)A + (size_t)grow * kb + koff + ch * 16;
                dst = sb + plane * 16384 + SWZ(row * 128 + ch * 16);
            } else {                        // B: 256 rows x 8 ch
                int idx   = q - 2048;
                int row   = idx >> 3;
                int ch    = idx & 7;
                int grow  = bn + row;
                src = (const char*)B + (size_t)grow * kb + koff + ch * 16;
                dst = sb + 32768 + SWZ(row * 128 + ch * 16);
            }
            cp_async16(dst, src);
        }
        cp_commit();
    };

    // prologue: two chunks in flight (once per CTA)
    load_chunk(0);
    if (gq_total > 1) load_chunk(1);

    const int lane = tid & 31;
    const int sub  = wid & 3;
    const int tI   = wid >> 2;
    const uint32_t woff = ((uint32_t)sub) << 21;

    int gq = 0;
    for (int it = 0; it < myntiles; ++it) {
        int t  = blockIdx.x + it * gridDim.x;
        int bn = (t % nN) << 8;
        int bm = (t / nN) << 8;

        for (int c = 0; c < NCHUNK; ++c, ++gq) {
            if (gq + 1 < gq_total) cp_wait1();
            else                   cp_wait0();
            fence_proxy_async_cta();
            tc_fence_before();
            __syncthreads();

            if (gq + 2 < gq_total) {
                if (gq >= 1) mbar_wait(bMma, (uint32_t)((gq - 1) & 1));
                load_chunk(gq + 2);
            }

            if (wid == 0) {
                tc_fence_after();
                if (elect_one_pred()) {
                    uint32_t sb = stage + (uint32_t)(gq % NSTG) * STAGEB;
                    uint64_t dA0 = make_desc(sb);
                    uint64_t dA1 = make_desc(sb + 16384);
                    uint64_t dB  = make_desc(sb + 32768);
                    #pragma unroll
                    for (int ks = 0; ks < 4; ++ks) {
                        uint64_t o = (uint64_t)(ks * 2);
                        uint32_t acc = (c > 0 || ks > 0) ? 1u : 0u;
                        mma_f16_ss(tmem,       dA0 + o, dB + o, IDESC_V, acc);
                        mma_f16_ss(tmem + 256, dA1 + o, dB + o, IDESC_V, acc);
                    }
                    mma_commit(bMma);
                }
            }
        }

        // ---------------- epilogue for tile t (next tile's loads stream) ----
        mbar_wait(bMma, (uint32_t)((gq - 1) & 1));
        __syncthreads();
        tc_fence_after();

        const int row = bm + tI * 128 + sub * 32 + lane;
        #pragma unroll 1
        for (int b = 0; b < 8; ++b) {
            uint32_t r[32];
            TCGEN05_LD_X32(r, tmem + tI * 256 + b * 32 + woff);
            tmem_wait_ld();
            int col0 = bn + b * 32;
            if (mode) {
                __align__(16) __half hv[32];
                #pragma unroll
                for (int j = 0; j < 32; ++j) {
                    float v = __uint_as_float(r[j]) + bias[col0 + j];
                    hv[j] = __float2half_rn(gelu_exact(v));
                }
                uint4* dh = (uint4*)(outH + (size_t)row * Nfull + col0);
                #pragma unroll
                for (int u = 0; u < 4; ++u) dh[u] = ((uint4*)hv)[u];
            } else {
                float* dp = outF + (size_t)row * Nfull + col0;
                #pragma unroll
                for (int j = 0; j < 32; j += 4) {
                    float4 v;
                    v.x = __uint_as_float(r[j + 0]) + bias[col0 + j + 0];
                    v.y = __uint_as_float(r[j + 1]) + bias[col0 + j + 1];
                    v.z = __uint_as_float(r[j + 2]) + bias[col0 + j + 2];
                    v.w = __uint_as_float(r[j + 3]) + bias[col0 + j + 3];
                    *(float4*)(dp + j) = v;
                }
            }
        }

        tc_fence_before();
        __syncthreads();   // all warps done reading TMEM before next tile MMA
    }

    if (tid == 0) mbar_inval(bMma);
    __syncthreads();
    if (wid == 0) tmem_dealloc(tmem, 512);

#else  // ------------------- FFMA fallback (plain sm_103 pass) ---------------
    extern __shared__ char dsm_raw[];
    float* As = (float*)dsm_raw;                  // [16][128]
    float* Bs = (float*)(dsm_raw + 16 * 128 * 4); // [16][64]

    const int tid = threadIdx.x & 127;
    const int ty  = tid >> 4;
    const int tx  = tid & 15;
    if (threadIdx.x >= 128) return;

    const int nN = Nfull >> 8;
    const int total_tiles = (M >> 8) * nN;

    for (int t = blockIdx.x; t < total_tiles; t += gridDim.x) {
        const int bn0 = (t % nN) << 8;
        const int bmT = (t / nN) << 8;
        for (int msub = 0; msub < 2; ++msub) {
            const int bm = bmT + msub * 128;
            for (int ns = 0; ns < 4; ++ns) {
                int bn = bn0 + ns * 64;
                float acc[16][4];
                #pragma unroll
                for (int i = 0; i < 16; i++)
                    #pragma unroll
                    for (int j = 0; j < 4; j++) acc[i][j] = 0.f;

                for (int k0 = 0; k0 < K; k0 += 16) {
                    #pragma unroll
                    for (int i = 0; i < 16; i++) {
                        int idx = tid + 128 * i;
                        int row = idx >> 4, kk = idx & 15;
                        As[kk * 128 + row] = __half2float(A[(size_t)(bm + row) * K + k0 + kk]);
                    }
                    #pragma unroll
                    for (int i = 0; i < 8; i++) {
                        int idx = tid + 128 * i;
                        int n = idx >> 4, kk = idx & 15;
                        Bs[kk * 64 + n] = __half2float(B[(size_t)(bn + n) * K + k0 + kk]);
                    }
                    __syncthreads();
                    #pragma unroll
                    for (int kk = 0; kk < 16; kk++) {
                        float bvals[4];
                        #pragma unroll
                        for (int j = 0; j < 4; j++) bvals[j] = Bs[kk * 64 + tx * 4 + j];
                        #pragma unroll
                        for (int i = 0; i < 16; i++) {
                            float av = As[kk * 128 + ty * 16 + i];
                            #pragma unroll
                            for (int j = 0; j < 4; j++) acc[i][j] += av * bvals[j];
                        }
                    }
                    __syncthreads();
                }

                #pragma unroll
                for (int i = 0; i < 16; i++) {
                    int row = bm + ty * 16 + i;
                    #pragma unroll
                    for (int j = 0; j < 4; j++) {
                        int col = bn + tx * 4 + j;
                        float v = acc[i][j] + bias[col];
                        if (mode) outH[(size_t)row * Nfull + col] = __float2half_rn(gelu_exact(v));
                        else      outF[(size_t)row * Nfull + col] = v;
                    }
                }
                __syncthreads();
            }
        }
    }
#endif
}

// ----------------------------------------------------------------------------
extern "C" void kernel_launch(void* const* d_in, const int* in_sizes, int n_in,
                              void* d_out, int out_size)
{
    const float* vf    = (const float*)d_in[0];
    const int*   ss    = (const int*)  d_in[1];
    const float* gamma = (const float*)d_in[2];
    const float* beta  = (const float*)d_in[3];
    const float* w1    = (const float*)d_in[4];
    const float* b1    = (const float*)d_in[5];
    const float* w2    = (const float*)d_in[6];
    const float* b2    = (const float*)d_in[7];
    float* out = (float*)d_out;

    int total_tokens = in_sizes[0] / HDIM;
    int M = total_tokens / 4;
    if (M > MAXM) M = MAXM;

    __half *dX, *dH, *dW1, *dW2;
    cudaGetSymbolAddress((void**)&dX,  g_X);
    cudaGetSymbolAddress((void**)&dH,  g_H);
    cudaGetSymbolAddress((void**)&dW1, g_W1);
    cudaGetSymbolAddress((void**)&dW2, g_W2);

    int sms = 148;
    cudaDeviceGetAttribute(&sms, cudaDevAttrMultiProcessorCount, 0);

    cudaFuncSetAttribute(gemm_kernel, cudaFuncAttributeMaxDynamicSharedMemorySize, DSMEMB);

    meta_kernel<<<1, 32>>>(ss);
    gather_ln_kernel<<<M, 256>>>(vf, gamma, beta);

    dim3 wb(32, 8);
    wconv_kernel<<<dim3(PH / 32, IC / 32), wb>>>(w1, dW1, IC, PH);
    wconv_kernel<<<dim3(TH / 32, PH / 32), wb>>>(w2, dW2, PH, TH);

    int tt1 = (M / 256) * (PH / 256);
    int g1  = tt1 < sms ? tt1 : sms;
    gemm_kernel<<<g1, 256, DSMEMB>>>(dX, dW1, b1, nullptr, dH, M, IC, PH, 1);

    int tt2 = (M / 256) * (TH / 256);
    int g2  = tt2 < sms ? tt2 : sms;
    gemm_kernel<<<g2, 256, DSMEMB>>>(dH, dW2, b2, out, nullptr, M, PH, TH, 0);
}